// round 11
// baseline (speedup 1.0000x reference)
#include <cuda_runtime.h>
#include <cuda_fp16.h>
#include <cstdint>

// Problem constants (fixed by dataset)
#define B_DIM   2048
#define IN_DIM  1024
#define H_DIM   2048
#define OUT_DIM 1024
#define BSB     32
#define RBX     64
#define NNZ     (64 * 32)

// ---------------------------------------------------------------------------
// Device globals (no allocation allowed). Plain fp16 everywhere.
// ---------------------------------------------------------------------------
__device__ __half g_x[(size_t)B_DIM * IN_DIM];
__device__ __half g_w1[(size_t)H_DIM * IN_DIM];
__device__ __half g_w3[(size_t)OUT_DIM * H_DIM];
__device__ __half g_vals[(size_t)NNZ * BSB * BSB];
__device__ __half g_h1[(size_t)B_DIM * H_DIM];
__device__ __half g_h2[(size_t)B_DIM * H_DIM];

// ---------------------------------------------------------------------------
// Helpers
// ---------------------------------------------------------------------------
__device__ __forceinline__ uint32_t smem_u32(const void* p) {
    uint32_t a;
    asm("{ .reg .u64 t; cvta.to.shared.u64 t, %1; cvt.u32.u64 %0, t; }"
        : "=r"(a) : "l"(p));
    return a;
}

__device__ __forceinline__ void cp16(uint32_t dst, const void* src) {
    asm volatile("cp.async.cg.shared.global [%0], [%1], 16;"
                 :: "r"(dst), "l"(src) : "memory");
}
#define CP_COMMIT() asm volatile("cp.async.commit_group;" ::: "memory")
#define CP_WAIT(N)  asm volatile("cp.async.wait_group %0;" :: "n"(N) : "memory")

__device__ __forceinline__ void ldsm_x4(uint32_t (&r)[4], uint32_t addr) {
    asm volatile("ldmatrix.sync.aligned.m8n8.x4.shared.b16 {%0,%1,%2,%3}, [%4];"
                 : "=r"(r[0]), "=r"(r[1]), "=r"(r[2]), "=r"(r[3]) : "r"(addr));
}

__device__ __forceinline__ void mma_fp16(float c[4], const uint32_t a[4],
                                         const uint32_t b[2]) {
    asm volatile(
        "mma.sync.aligned.m16n8k16.row.col.f32.f16.f16.f32 "
        "{%0,%1,%2,%3}, {%4,%5,%6,%7}, {%8,%9}, {%0,%1,%2,%3};"
        : "+f"(c[0]), "+f"(c[1]), "+f"(c[2]), "+f"(c[3])
        : "r"(a[0]), "r"(a[1]), "r"(a[2]), "r"(a[3]), "r"(b[0]), "r"(b[1]));
}

// ---------------------------------------------------------------------------
// Prep kernel: convert 4 fp32 arrays to plain fp16 (blockIdx.y selects array)
// ---------------------------------------------------------------------------
struct PrepArgs {
    const float4* src[4];
    uint2* dst[4];
};

__global__ __launch_bounds__(256) void prep_kernel(PrepArgs args, int n4)
{
    const int a = blockIdx.y;
    const int i = blockIdx.x * 256 + threadIdx.x;
    if (i >= n4) return;
    float4 v = args.src[a][i];
    __half2 h0 = __floats2half2_rn(v.x, v.y);
    __half2 h1 = __floats2half2_rn(v.z, v.w);
    uint2 u; u.x = *(uint32_t*)&h0; u.y = *(uint32_t*)&h1;
    args.dst[a][i] = u;
}

// ---------------------------------------------------------------------------
// Dense GEMM (NT): C = act(A @ B^T + bias). Plain fp16, fp32 accum.
// CTA 128x128, 4 warps (64x64 warp tiles), K-chunk 32.
// 3-stage cp.async pipeline, ONE __syncthreads per chunk. (R10 config - at floor)
// MODE 0: fp32 out + bias.  MODE 1: relu, write fp16.
// ---------------------------------------------------------------------------
#define ROWB   80                    // 64B data + 16B pad
#define D_AT   (128 * ROWB)          // 10240 B per matrix tile
#define DSTG   (2 * D_AT)            // A, B -> 20480 B per stage
#define DS     3
#define D_SMEM (DS * DSTG)           // 61440 B

template <int MODE>
__global__ __launch_bounds__(128, 2) void gemm_fp16_kernel(
    const __half* __restrict__ A, const __half* __restrict__ Bm,
    const float* __restrict__ bias, float* __restrict__ Cf,
    __half* __restrict__ Ch, int N, int K)
{
    extern __shared__ char sm[];
    const uint32_t sb = smem_u32(sm);
    const int tid  = threadIdx.x;
    const int lane = tid & 31;
    const int wid  = tid >> 5;
    const int brow = blockIdx.y * 128;
    const int bcol = blockIdx.x * 128;
    const int wm = (wid >> 1) * 64;
    const int wn = (wid & 1) * 64;
    const int chunks = K / 32;

    float acc[4][8][4];
#pragma unroll
    for (int i = 0; i < 4; i++)
#pragma unroll
        for (int j = 0; j < 8; j++)
#pragma unroll
            for (int r = 0; r < 4; r++) acc[i][j][r] = 0.0f;

    auto issue = [&](int ki, int buf) {
        const int k0 = ki * 32;
        const uint32_t bufo = sb + (uint32_t)buf * DSTG;
#pragma unroll
        for (int t = 0; t < 4; t++) {
            const int seg = tid + t * 128;
            const int row = seg >> 2, s = seg & 3;
            const uint32_t d = bufo + row * ROWB + s * 16;
            cp16(d,        A  + (size_t)(brow + row) * K + k0 + s * 8);
            cp16(d + D_AT, Bm + (size_t)(bcol + row) * K + k0 + s * 8);
        }
    };

    issue(0, 0); CP_COMMIT();
    issue(1, 1); CP_COMMIT();

    const uint32_t aoff = (wm + (lane & 15)) * ROWB + ((lane >> 4) & 1) * 16;
    const uint32_t boff = (wn + ((lane >> 4) & 1) * 8 + (lane & 7)) * ROWB +
                          ((lane >> 3) & 1) * 16;

    int rbuf = 0, wbuf = 2;
    for (int kc = 0; kc < chunks; kc++) {
        CP_WAIT(1);
        __syncthreads();
        if (kc + 2 < chunks) issue(kc + 2, wbuf);
        CP_COMMIT();

        const uint32_t base = sb + (uint32_t)rbuf * DSTG;
#pragma unroll
        for (int ks = 0; ks < 2; ks++) {
            uint32_t bq[4][4];
#pragma unroll
            for (int jp = 0; jp < 4; jp++)
                ldsm_x4(bq[jp], base + D_AT + boff + jp * (16 * ROWB) + ks * 32);
            uint32_t af[4][4];
#pragma unroll
            for (int i = 0; i < 4; i++)
                ldsm_x4(af[i], base + aoff + i * (16 * ROWB) + ks * 32);
#pragma unroll
            for (int i = 0; i < 4; i++)
#pragma unroll
                for (int j = 0; j < 8; j++)
                    mma_fp16(acc[i][j], af[i], &bq[j >> 1][(j & 1) * 2]);
        }
        rbuf = (rbuf == 2) ? 0 : rbuf + 1;
        wbuf = (wbuf == 2) ? 0 : wbuf + 1;
    }

    // epilogue
#pragma unroll
    for (int i = 0; i < 4; i++) {
        const int r0 = brow + wm + i * 16 + (lane >> 2);
#pragma unroll
        for (int j = 0; j < 8; j++) {
            const int c0 = bcol + wn + j * 8 + 2 * (lane & 3);
            const float bx = __ldg(&bias[c0]), by = __ldg(&bias[c0 + 1]);
            float v00 = acc[i][j][0] + bx, v01 = acc[i][j][1] + by;
            float v10 = acc[i][j][2] + bx, v11 = acc[i][j][3] + by;
            if (MODE == 0) {
                *(float2*)(Cf + (size_t)r0 * N + c0)       = make_float2(v00, v01);
                *(float2*)(Cf + (size_t)(r0 + 8) * N + c0) = make_float2(v10, v11);
            } else {
                v00 = fmaxf(v00, 0.f); v01 = fmaxf(v01, 0.f);
                v10 = fmaxf(v10, 0.f); v11 = fmaxf(v11, 0.f);
                *(__half2*)(Ch + (size_t)r0 * N + c0)       = __floats2half2_rn(v00, v01);
                *(__half2*)(Ch + (size_t)(r0 + 8) * N + c0) = __floats2half2_rn(v10, v11);
            }
        }
    }
}

// ---------------------------------------------------------------------------
// BSR layer: per (batch-tile 128, row-block rb):
//   h2[., rb*32:+32] = relu( sum_p h1[., col_p*32:+32] @ vals[p]^T + b2 )
// Plain fp16. CTA = 64 threads (2 warps, 64x32 warp tiles), batch tile 128.
// Grid 16x64 = 1024 CTAs (2048 HMMA each) -> near-perfect SM balance.
// 4-stage cp.async, ONE sync per block; 4 CTAs/SM co-resident.
// ---------------------------------------------------------------------------
#define S_AT   (128 * ROWB)                 // 10240 B (A tile, 128 batch rows)
#define S_BT   (32 * ROWB)                  // 2560 B  (B tile)
#define SSTG   (S_AT + S_BT)                // 12800 B per stage
#define SS     4
#define S_SMEM (SS * SSTG)                  // 51200 B

__global__ __launch_bounds__(64, 4) void bsr_fp16_kernel(
    const __half* __restrict__ h1, const int* __restrict__ crow,
    const int* __restrict__ cols, const __half* __restrict__ vals,
    const float* __restrict__ bias, __half* __restrict__ h2)
{
    extern __shared__ char sm[];
    const uint32_t sb = smem_u32(sm);
    const int tid  = threadIdx.x;
    const int lane = tid & 31;
    const int wid  = tid >> 5;
    const int b0 = blockIdx.x * 128;
    const int rb = blockIdx.y;
    const int wm = wid * 64;    // 2 warps x 64 batch rows

    float acc[4][4][4];
#pragma unroll
    for (int i = 0; i < 4; i++)
#pragma unroll
        for (int j = 0; j < 4; j++)
#pragma unroll
            for (int r = 0; r < 4; r++) acc[i][j][r] = 0.0f;

    const int s0 = __ldg(&crow[rb]);
    const int nblk = __ldg(&crow[rb + 1]) - s0;

    auto issue = [&](int ki, int buf) {
        const int p = s0 + ki;
        const int cb = __ldg(&cols[p]);
        const uint32_t bufo = sb + (uint32_t)buf * SSTG;
        // A: 128 rows x 4 segs = 512 segs / 64 threads = 8 each
#pragma unroll
        for (int t = 0; t < 8; t++) {
            const int seg = tid + t * 64;
            const int row = seg >> 2, s = seg & 3;
            cp16(bufo + row * ROWB + s * 16,
                 h1 + (size_t)(b0 + row) * H_DIM + cb * 32 + s * 8);
        }
        // B: 32 rows x 4 segs = 128 segs / 64 threads = 2 each
#pragma unroll
        for (int t = 0; t < 2; t++) {
            const int seg = tid + t * 64;
            const int row = seg >> 2, s = seg & 3;
            cp16(bufo + S_AT + row * ROWB + s * 16,
                 vals + (size_t)p * (BSB * BSB) + row * BSB + s * 8);
        }
    };

    issue(0, 0); CP_COMMIT();
    if (nblk > 1) issue(1, 1);
    CP_COMMIT();
    if (nblk > 2) issue(2, 2);
    CP_COMMIT();

    const uint32_t aoff = (wm + (lane & 15)) * ROWB + ((lane >> 4) & 1) * 16;
    const uint32_t boff = (((lane >> 4) & 1) * 8 + (lane & 7)) * ROWB +
                          ((lane >> 3) & 1) * 16;

    int rbuf = 0, wbuf = 3;
    for (int it = 0; it < nblk; it++) {
        CP_WAIT(2);
        __syncthreads();
        if (it + 3 < nblk) issue(it + 3, wbuf);
        CP_COMMIT();

        const uint32_t base = sb + (uint32_t)rbuf * SSTG;
#pragma unroll
        for (int ks = 0; ks < 2; ks++) {
            uint32_t bq[2][4];
#pragma unroll
            for (int jp = 0; jp < 2; jp++)
                ldsm_x4(bq[jp], base + S_AT + boff + jp * (16 * ROWB) + ks * 32);
            uint32_t af[4][4];
#pragma unroll
            for (int i = 0; i < 4; i++)
                ldsm_x4(af[i], base + aoff + i * (16 * ROWB) + ks * 32);
#pragma unroll
            for (int i = 0; i < 4; i++)
#pragma unroll
                for (int j = 0; j < 4; j++)
                    mma_fp16(acc[i][j], af[i], &bq[j >> 1][(j & 1) * 2]);
        }
        rbuf = (rbuf == 3) ? 0 : rbuf + 1;
        wbuf = (wbuf == 3) ? 0 : wbuf + 1;
    }

    // epilogue: bias + relu -> fp16
#pragma unroll
    for (int i = 0; i < 4; i++) {
        const int r0 = b0 + wm + i * 16 + (lane >> 2);
#pragma unroll
        for (int j = 0; j < 4; j++) {
            const int c0 = rb * 32 + j * 8 + 2 * (lane & 3);
            const float bx = __ldg(&bias[c0]), by = __ldg(&bias[c0 + 1]);
            float v00 = fmaxf(acc[i][j][0] + bx, 0.f);
            float v01 = fmaxf(acc[i][j][1] + by, 0.f);
            float v10 = fmaxf(acc[i][j][2] + bx, 0.f);
            float v11 = fmaxf(acc[i][j][3] + by, 0.f);
            *(__half2*)(h2 + (size_t)r0 * H_DIM + c0)       = __floats2half2_rn(v00, v01);
            *(__half2*)(h2 + (size_t)(r0 + 8) * H_DIM + c0) = __floats2half2_rn(v10, v11);
        }
    }
}

// ---------------------------------------------------------------------------
// Launcher
// ---------------------------------------------------------------------------
extern "C" void kernel_launch(void* const* d_in, const int* in_sizes, int n_in,
                              void* d_out, int out_size)
{
    const float* x    = (const float*)d_in[0];
    const float* W1   = (const float*)d_in[1];
    const float* b1   = (const float*)d_in[2];
    const int*   crow = (const int*)d_in[3];
    const int*   cols = (const int*)d_in[4];
    const float* vals = (const float*)d_in[5];
    const float* b2   = (const float*)d_in[6];
    const float* W3   = (const float*)d_in[7];
    const float* b3   = (const float*)d_in[8];
    float* out = (float*)d_out;

    __half *xh, *w1, *w3, *vf, *h1, *h2;
    cudaGetSymbolAddress((void**)&xh, g_x);
    cudaGetSymbolAddress((void**)&w1, g_w1);
    cudaGetSymbolAddress((void**)&w3, g_w3);
    cudaGetSymbolAddress((void**)&vf, g_vals);
    cudaGetSymbolAddress((void**)&h1, g_h1);
    cudaGetSymbolAddress((void**)&h2, g_h2);

    cudaFuncSetAttribute(gemm_fp16_kernel<0>,
                         cudaFuncAttributeMaxDynamicSharedMemorySize, D_SMEM);
    cudaFuncSetAttribute(gemm_fp16_kernel<1>,
                         cudaFuncAttributeMaxDynamicSharedMemorySize, D_SMEM);
    cudaFuncSetAttribute(bsr_fp16_kernel,
                         cudaFuncAttributeMaxDynamicSharedMemorySize, S_SMEM);

    // Prep: convert x, W1, W3, vals to fp16 (each 2M elements = 512K float4)
    const int n4 = (B_DIM * IN_DIM) / 4;
    PrepArgs pa;
    pa.src[0] = (const float4*)x;    pa.dst[0] = (uint2*)xh;
    pa.src[1] = (const float4*)W1;   pa.dst[1] = (uint2*)w1;
    pa.src[2] = (const float4*)W3;   pa.dst[2] = (uint2*)w3;
    pa.src[3] = (const float4*)vals; pa.dst[3] = (uint2*)vf;
    prep_kernel<<<dim3(n4 / 256, 4), 256>>>(pa, n4);

    // Layer 1: h1 = relu(x @ W1^T + b1) -> fp16   [grid 16x16 = 256]
    gemm_fp16_kernel<1><<<dim3(H_DIM / 128, B_DIM / 128), 128, D_SMEM>>>(
        xh, w1, b1, nullptr, h1, H_DIM, IN_DIM);

    // Layer 2: h2 = relu(BSR(h1) + b2) -> fp16    [grid 16x64 = 1024]
    bsr_fp16_kernel<<<dim3(B_DIM / 128, RBX), 64, S_SMEM>>>(
        h1, crow, cols, vf, b2, h2);

    // Layer 3: out = h2 @ W3^T + b3 (fp32)        [grid 8x16 = 128]
    gemm_fp16_kernel<0><<<dim3(OUT_DIM / 128, B_DIM / 128), 128, D_SMEM>>>(
        h2, w3, b3, out, nullptr, OUT_DIM, H_DIM);
}

// round 12
// speedup vs baseline: 1.0227x; 1.0227x over previous
#include <cuda_runtime.h>
#include <cuda_fp16.h>
#include <cstdint>

// Problem constants (fixed by dataset)
#define B_DIM   2048
#define IN_DIM  1024
#define H_DIM   2048
#define OUT_DIM 1024
#define BSB     32
#define RBX     64
#define NNZ     (64 * 32)

// ---------------------------------------------------------------------------
// Device globals (no allocation allowed). Plain fp16 everywhere.
// h1 is stored COLUMN-BLOCK-MAJOR: h1b[cb][row][0..31]  (cb = col/32)
// so the BSR gather of one (cb, batch-tile) is a contiguous 16KB region.
// ---------------------------------------------------------------------------
__device__ __half g_x[(size_t)B_DIM * IN_DIM];
__device__ __half g_w1[(size_t)H_DIM * IN_DIM];
__device__ __half g_w3[(size_t)OUT_DIM * H_DIM];
__device__ __half g_vals[(size_t)NNZ * BSB * BSB];
__device__ __half g_h1[(size_t)B_DIM * H_DIM];   // blocked layout
__device__ __half g_h2[(size_t)B_DIM * H_DIM];   // row-major
#define H1_BLK ((size_t)B_DIM * BSB)             // elems per column block

// ---------------------------------------------------------------------------
// Helpers
// ---------------------------------------------------------------------------
__device__ __forceinline__ uint32_t smem_u32(const void* p) {
    uint32_t a;
    asm("{ .reg .u64 t; cvta.to.shared.u64 t, %1; cvt.u32.u64 %0, t; }"
        : "=r"(a) : "l"(p));
    return a;
}

__device__ __forceinline__ void cp16(uint32_t dst, const void* src) {
    asm volatile("cp.async.cg.shared.global [%0], [%1], 16;"
                 :: "r"(dst), "l"(src) : "memory");
}
#define CP_COMMIT() asm volatile("cp.async.commit_group;" ::: "memory")
#define CP_WAIT(N)  asm volatile("cp.async.wait_group %0;" :: "n"(N) : "memory")

__device__ __forceinline__ void ldsm_x4(uint32_t (&r)[4], uint32_t addr) {
    asm volatile("ldmatrix.sync.aligned.m8n8.x4.shared.b16 {%0,%1,%2,%3}, [%4];"
                 : "=r"(r[0]), "=r"(r[1]), "=r"(r[2]), "=r"(r[3]) : "r"(addr));
}

__device__ __forceinline__ void mma_fp16(float c[4], const uint32_t a[4],
                                         const uint32_t b[2]) {
    asm volatile(
        "mma.sync.aligned.m16n8k16.row.col.f32.f16.f16.f32 "
        "{%0,%1,%2,%3}, {%4,%5,%6,%7}, {%8,%9}, {%0,%1,%2,%3};"
        : "+f"(c[0]), "+f"(c[1]), "+f"(c[2]), "+f"(c[3])
        : "r"(a[0]), "r"(a[1]), "r"(a[2]), "r"(a[3]), "r"(b[0]), "r"(b[1]));
}

// ---------------------------------------------------------------------------
// Prep kernel: convert 4 fp32 arrays to plain fp16 (blockIdx.y selects array)
// ---------------------------------------------------------------------------
struct PrepArgs {
    const float4* src[4];
    uint2* dst[4];
};

__global__ __launch_bounds__(256) void prep_kernel(PrepArgs args, int n4)
{
    const int a = blockIdx.y;
    const int i = blockIdx.x * 256 + threadIdx.x;
    if (i >= n4) return;
    float4 v = args.src[a][i];
    __half2 h0 = __floats2half2_rn(v.x, v.y);
    __half2 h1 = __floats2half2_rn(v.z, v.w);
    uint2 u; u.x = *(uint32_t*)&h0; u.y = *(uint32_t*)&h1;
    args.dst[a][i] = u;
}

// ---------------------------------------------------------------------------
// Dense GEMM (NT): C = act(A @ B^T + bias). Plain fp16, fp32 accum.
// CTA 128x128, 4 warps (64x64 warp tiles), K-chunk 32.
// 3-stage cp.async pipeline, ONE __syncthreads per chunk.
// MODE 0: fp32 out + bias (row-major).
// MODE 1: relu, write fp16 in COLUMN-BLOCK-MAJOR layout (for BSR gather).
// ---------------------------------------------------------------------------
#define ROWB   80                    // 64B data + 16B pad
#define D_AT   (128 * ROWB)          // 10240 B per matrix tile
#define DSTG   (2 * D_AT)            // A, B -> 20480 B per stage
#define DS     3
#define D_SMEM (DS * DSTG)           // 61440 B

template <int MODE>
__global__ __launch_bounds__(128, 2) void gemm_fp16_kernel(
    const __half* __restrict__ A, const __half* __restrict__ Bm,
    const float* __restrict__ bias, float* __restrict__ Cf,
    __half* __restrict__ Ch, int N, int K)
{
    extern __shared__ char sm[];
    const uint32_t sb = smem_u32(sm);
    const int tid  = threadIdx.x;
    const int lane = tid & 31;
    const int wid  = tid >> 5;
    const int brow = blockIdx.y * 128;
    const int bcol = blockIdx.x * 128;
    const int wm = (wid >> 1) * 64;
    const int wn = (wid & 1) * 64;
    const int chunks = K / 32;

    float acc[4][8][4];
#pragma unroll
    for (int i = 0; i < 4; i++)
#pragma unroll
        for (int j = 0; j < 8; j++)
#pragma unroll
            for (int r = 0; r < 4; r++) acc[i][j][r] = 0.0f;

    auto issue = [&](int ki, int buf) {
        const int k0 = ki * 32;
        const uint32_t bufo = sb + (uint32_t)buf * DSTG;
#pragma unroll
        for (int t = 0; t < 4; t++) {
            const int seg = tid + t * 128;
            const int row = seg >> 2, s = seg & 3;
            const uint32_t d = bufo + row * ROWB + s * 16;
            cp16(d,        A  + (size_t)(brow + row) * K + k0 + s * 8);
            cp16(d + D_AT, Bm + (size_t)(bcol + row) * K + k0 + s * 8);
        }
    };

    issue(0, 0); CP_COMMIT();
    issue(1, 1); CP_COMMIT();

    const uint32_t aoff = (wm + (lane & 15)) * ROWB + ((lane >> 4) & 1) * 16;
    const uint32_t boff = (wn + ((lane >> 4) & 1) * 8 + (lane & 7)) * ROWB +
                          ((lane >> 3) & 1) * 16;

    int rbuf = 0, wbuf = 2;
    for (int kc = 0; kc < chunks; kc++) {
        CP_WAIT(1);
        __syncthreads();
        if (kc + 2 < chunks) issue(kc + 2, wbuf);
        CP_COMMIT();

        const uint32_t base = sb + (uint32_t)rbuf * DSTG;
#pragma unroll
        for (int ks = 0; ks < 2; ks++) {
            uint32_t bq[4][4];
#pragma unroll
            for (int jp = 0; jp < 4; jp++)
                ldsm_x4(bq[jp], base + D_AT + boff + jp * (16 * ROWB) + ks * 32);
            uint32_t af[4][4];
#pragma unroll
            for (int i = 0; i < 4; i++)
                ldsm_x4(af[i], base + aoff + i * (16 * ROWB) + ks * 32);
#pragma unroll
            for (int i = 0; i < 4; i++)
#pragma unroll
                for (int j = 0; j < 8; j++)
                    mma_fp16(acc[i][j], af[i], &bq[j >> 1][(j & 1) * 2]);
        }
        rbuf = (rbuf == 2) ? 0 : rbuf + 1;
        wbuf = (wbuf == 2) ? 0 : wbuf + 1;
    }

    // epilogue
#pragma unroll
    for (int i = 0; i < 4; i++) {
        const int r0 = brow + wm + i * 16 + (lane >> 2);
#pragma unroll
        for (int j = 0; j < 8; j++) {
            const int c0 = bcol + wn + j * 8 + 2 * (lane & 3);
            const float bx = __ldg(&bias[c0]), by = __ldg(&bias[c0 + 1]);
            float v00 = acc[i][j][0] + bx, v01 = acc[i][j][1] + by;
            float v10 = acc[i][j][2] + bx, v11 = acc[i][j][3] + by;
            if (MODE == 0) {
                *(float2*)(Cf + (size_t)r0 * N + c0)       = make_float2(v00, v01);
                *(float2*)(Cf + (size_t)(r0 + 8) * N + c0) = make_float2(v10, v11);
            } else {
                v00 = fmaxf(v00, 0.f); v01 = fmaxf(v01, 0.f);
                v10 = fmaxf(v10, 0.f); v11 = fmaxf(v11, 0.f);
                // column-block-major: h1b[cb][row][cw]
                const size_t pbase = (size_t)(c0 >> 5) * H1_BLK + (c0 & 31);
                *(__half2*)(Ch + pbase + (size_t)r0 * BSB) =
                    __floats2half2_rn(v00, v01);
                *(__half2*)(Ch + pbase + (size_t)(r0 + 8) * BSB) =
                    __floats2half2_rn(v10, v11);
            }
        }
    }
}

// ---------------------------------------------------------------------------
// BSR layer: per (batch-tile 256, row-block rb):
//   h2[., rb*32:+32] = relu( sum_p h1b[col_p][b0:b0+256][.] @ vals[p]^T + b2 )
// A-gather is now CONTIGUOUS 16KB per block (blocked h1 layout).
// Plain fp16. 4 warps (64x32 warp tiles), 3-stage cp.async, ONE sync/block.
// smem 69KB -> 2 CTAs/SM.
// ---------------------------------------------------------------------------
#define S_AT   (256 * ROWB)                 // 20480 B (A tile)
#define S_BT   (32 * ROWB)                  // 2560 B  (B tile)
#define SSTG   (S_AT + S_BT)                // 23040 B per stage
#define SS     3
#define S_SMEM (SS * SSTG)                  // 69120 B

__global__ __launch_bounds__(128, 2) void bsr_fp16_kernel(
    const __half* __restrict__ h1b, const int* __restrict__ crow,
    const int* __restrict__ cols, const __half* __restrict__ vals,
    const float* __restrict__ bias, __half* __restrict__ h2)
{
    extern __shared__ char sm[];
    const uint32_t sb = smem_u32(sm);
    const int tid  = threadIdx.x;
    const int lane = tid & 31;
    const int wid  = tid >> 5;
    const int b0 = blockIdx.x * 256;
    const int rb = blockIdx.y;
    const int wm = wid * 64;    // 4 warps x 64 batch rows

    float acc[4][4][4];
#pragma unroll
    for (int i = 0; i < 4; i++)
#pragma unroll
        for (int j = 0; j < 4; j++)
#pragma unroll
            for (int r = 0; r < 4; r++) acc[i][j][r] = 0.0f;

    const int s0 = __ldg(&crow[rb]);
    const int nblk = __ldg(&crow[rb + 1]) - s0;

    auto issue = [&](int ki, int buf) {
        const int p = s0 + ki;
        const int cb = __ldg(&cols[p]);
        const uint32_t bufo = sb + (uint32_t)buf * SSTG;
        // A: contiguous 16KB region h1b[cb][b0 .. b0+255][0..31]
        const __half* asrc = h1b + (size_t)cb * H1_BLK + (size_t)b0 * BSB;
#pragma unroll
        for (int t = 0; t < 8; t++) {
            const int seg = tid + t * 128;
            const int row = seg >> 2, s = seg & 3;
            cp16(bufo + row * ROWB + s * 16, asrc + (size_t)row * BSB + s * 8);
        }
        // B: 32 rows x 4 segs = 128 segs (one per thread)
        {
            const int row = tid >> 2, s = tid & 3;
            cp16(bufo + S_AT + row * ROWB + s * 16,
                 vals + (size_t)p * (BSB * BSB) + row * BSB + s * 8);
        }
    };

    issue(0, 0); CP_COMMIT();
    if (nblk > 1) issue(1, 1);
    CP_COMMIT();

    const uint32_t aoff = (wm + (lane & 15)) * ROWB + ((lane >> 4) & 1) * 16;
    const uint32_t boff = (((lane >> 4) & 1) * 8 + (lane & 7)) * ROWB +
                          ((lane >> 3) & 1) * 16;

    int rbuf = 0, wbuf = 2;
    for (int it = 0; it < nblk; it++) {
        CP_WAIT(1);
        __syncthreads();
        if (it + 2 < nblk) issue(it + 2, wbuf);
        CP_COMMIT();

        const uint32_t base = sb + (uint32_t)rbuf * SSTG;
#pragma unroll
        for (int ks = 0; ks < 2; ks++) {
            uint32_t bq[2][4];
#pragma unroll
            for (int jp = 0; jp < 2; jp++)
                ldsm_x4(bq[jp], base + S_AT + boff + jp * (16 * ROWB) + ks * 32);
            uint32_t af[4][4];
#pragma unroll
            for (int i = 0; i < 4; i++)
                ldsm_x4(af[i], base + aoff + i * (16 * ROWB) + ks * 32);
#pragma unroll
            for (int i = 0; i < 4; i++)
#pragma unroll
                for (int j = 0; j < 4; j++)
                    mma_fp16(acc[i][j], af[i], &bq[j >> 1][(j & 1) * 2]);
        }
        rbuf = (rbuf == 2) ? 0 : rbuf + 1;
        wbuf = (wbuf == 2) ? 0 : wbuf + 1;
    }

    // epilogue: bias + relu -> fp16 (row-major h2)
#pragma unroll
    for (int i = 0; i < 4; i++) {
        const int r0 = b0 + wm + i * 16 + (lane >> 2);
#pragma unroll
        for (int j = 0; j < 4; j++) {
            const int c0 = rb * 32 + j * 8 + 2 * (lane & 3);
            const float bx = __ldg(&bias[c0]), by = __ldg(&bias[c0 + 1]);
            float v00 = fmaxf(acc[i][j][0] + bx, 0.f);
            float v01 = fmaxf(acc[i][j][1] + by, 0.f);
            float v10 = fmaxf(acc[i][j][2] + bx, 0.f);
            float v11 = fmaxf(acc[i][j][3] + by, 0.f);
            *(__half2*)(h2 + (size_t)r0 * H_DIM + c0)       = __floats2half2_rn(v00, v01);
            *(__half2*)(h2 + (size_t)(r0 + 8) * H_DIM + c0) = __floats2half2_rn(v10, v11);
        }
    }
}

// ---------------------------------------------------------------------------
// Launcher
// ---------------------------------------------------------------------------
extern "C" void kernel_launch(void* const* d_in, const int* in_sizes, int n_in,
                              void* d_out, int out_size)
{
    const float* x    = (const float*)d_in[0];
    const float* W1   = (const float*)d_in[1];
    const float* b1   = (const float*)d_in[2];
    const int*   crow = (const int*)d_in[3];
    const int*   cols = (const int*)d_in[4];
    const float* vals = (const float*)d_in[5];
    const float* b2   = (const float*)d_in[6];
    const float* W3   = (const float*)d_in[7];
    const float* b3   = (const float*)d_in[8];
    float* out = (float*)d_out;

    __half *xh, *w1, *w3, *vf, *h1, *h2;
    cudaGetSymbolAddress((void**)&xh, g_x);
    cudaGetSymbolAddress((void**)&w1, g_w1);
    cudaGetSymbolAddress((void**)&w3, g_w3);
    cudaGetSymbolAddress((void**)&vf, g_vals);
    cudaGetSymbolAddress((void**)&h1, g_h1);
    cudaGetSymbolAddress((void**)&h2, g_h2);

    cudaFuncSetAttribute(gemm_fp16_kernel<0>,
                         cudaFuncAttributeMaxDynamicSharedMemorySize, D_SMEM);
    cudaFuncSetAttribute(gemm_fp16_kernel<1>,
                         cudaFuncAttributeMaxDynamicSharedMemorySize, D_SMEM);
    cudaFuncSetAttribute(bsr_fp16_kernel,
                         cudaFuncAttributeMaxDynamicSharedMemorySize, S_SMEM);

    // Prep: convert x, W1, W3, vals to fp16 (each 2M elements = 512K float4)
    const int n4 = (B_DIM * IN_DIM) / 4;
    PrepArgs pa;
    pa.src[0] = (const float4*)x;    pa.dst[0] = (uint2*)xh;
    pa.src[1] = (const float4*)W1;   pa.dst[1] = (uint2*)w1;
    pa.src[2] = (const float4*)W3;   pa.dst[2] = (uint2*)w3;
    pa.src[3] = (const float4*)vals; pa.dst[3] = (uint2*)vf;
    prep_kernel<<<dim3(n4 / 256, 4), 256>>>(pa, n4);

    // Layer 1: h1 = relu(x @ W1^T + b1) -> fp16, column-block-major
    gemm_fp16_kernel<1><<<dim3(H_DIM / 128, B_DIM / 128), 128, D_SMEM>>>(
        xh, w1, b1, nullptr, h1, H_DIM, IN_DIM);

    // Layer 2: h2 = relu(BSR(h1b) + b2) -> fp16 row-major   [grid 8x64]
    bsr_fp16_kernel<<<dim3(B_DIM / 256, RBX), 128, S_SMEM>>>(
        h1, crow, cols, vf, b2, h2);

    // Layer 3: out = h2 @ W3^T + b3 (fp32)                  [grid 8x16]
    gemm_fp16_kernel<0><<<dim3(OUT_DIM / 128, B_DIM / 128), 128, D_SMEM>>>(
        h2, w3, b3, out, nullptr, OUT_DIM, H_DIM);
}

// round 13
// speedup vs baseline: 1.0412x; 1.0181x over previous
#include <cuda_runtime.h>
#include <cuda_fp16.h>
#include <cstdint>

// Problem constants (fixed by dataset)
#define B_DIM   2048
#define IN_DIM  1024
#define H_DIM   2048
#define OUT_DIM 1024
#define BSB     32
#define RBX     64
#define NNZ     (64 * 32)

// ---------------------------------------------------------------------------
// Device globals (no allocation allowed). Plain fp16 everywhere.
// h1 is stored COLUMN-BLOCK-MAJOR: h1b[cb][row][0..31]  (cb = col/32)
// ---------------------------------------------------------------------------
__device__ __half g_x[(size_t)B_DIM * IN_DIM];
__device__ __half g_w1[(size_t)H_DIM * IN_DIM];
__device__ __half g_w3[(size_t)OUT_DIM * H_DIM];
__device__ __half g_vals[(size_t)NNZ * BSB * BSB];
__device__ __half g_h1[(size_t)B_DIM * H_DIM];   // blocked layout
__device__ __half g_h2[(size_t)B_DIM * H_DIM];   // row-major
#define H1_BLK ((size_t)B_DIM * BSB)             // elems per column block

// ---------------------------------------------------------------------------
// Helpers
// ---------------------------------------------------------------------------
__device__ __forceinline__ uint32_t smem_u32(const void* p) {
    uint32_t a;
    asm("{ .reg .u64 t; cvta.to.shared.u64 t, %1; cvt.u32.u64 %0, t; }"
        : "=r"(a) : "l"(p));
    return a;
}

__device__ __forceinline__ void cp16(uint32_t dst, const void* src) {
    asm volatile("cp.async.cg.shared.global [%0], [%1], 16;"
                 :: "r"(dst), "l"(src) : "memory");
}
#define CP_COMMIT() asm volatile("cp.async.commit_group;" ::: "memory")
#define CP_WAIT(N)  asm volatile("cp.async.wait_group %0;" :: "n"(N) : "memory")

__device__ __forceinline__ void ldsm_x4(uint32_t (&r)[4], uint32_t addr) {
    asm volatile("ldmatrix.sync.aligned.m8n8.x4.shared.b16 {%0,%1,%2,%3}, [%4];"
                 : "=r"(r[0]), "=r"(r[1]), "=r"(r[2]), "=r"(r[3]) : "r"(addr));
}

__device__ __forceinline__ void mma_fp16(float c[4], const uint32_t a[4],
                                         const uint32_t b[2]) {
    asm volatile(
        "mma.sync.aligned.m16n8k16.row.col.f32.f16.f16.f32 "
        "{%0,%1,%2,%3}, {%4,%5,%6,%7}, {%8,%9}, {%0,%1,%2,%3};"
        : "+f"(c[0]), "+f"(c[1]), "+f"(c[2]), "+f"(c[3])
        : "r"(a[0]), "r"(a[1]), "r"(a[2]), "r"(a[3]), "r"(b[0]), "r"(b[1]));
}

// ---------------------------------------------------------------------------
// Prep kernel: convert 4 fp32 arrays to plain fp16 (blockIdx.y selects array)
// ---------------------------------------------------------------------------
struct PrepArgs {
    const float4* src[4];
    uint2* dst[4];
};

__global__ __launch_bounds__(256) void prep_kernel(PrepArgs args, int n4)
{
    const int a = blockIdx.y;
    const int i = blockIdx.x * 256 + threadIdx.x;
    if (i >= n4) return;
    float4 v = args.src[a][i];
    __half2 h0 = __floats2half2_rn(v.x, v.y);
    __half2 h1 = __floats2half2_rn(v.z, v.w);
    uint2 u; u.x = *(uint32_t*)&h0; u.y = *(uint32_t*)&h1;
    args.dst[a][i] = u;
}

// ---------------------------------------------------------------------------
// Dense GEMM (NT): C = act(A @ B^T + bias). Plain fp16, fp32 accum.
// CTA 128x128, 4 warps (64x64 warp tiles), K-chunk 32.
// 3-stage cp.async pipeline, ONE __syncthreads per chunk.
// MODE 0: fp32 out + bias (row-major).
// MODE 1: relu, fp16 column-block-major output via smem-staged coalesced
//         stores (16B segments contiguous in the blocked layout).
// ---------------------------------------------------------------------------
#define ROWB   80                    // 64B data + 16B pad
#define D_AT   (128 * ROWB)          // 10240 B per matrix tile
#define DSTG   (2 * D_AT)            // A, B -> 20480 B per stage
#define DS     3
#define D_SMEM (DS * DSTG)           // 61440 B
#define EP_ROWB 272                  // epilogue staging row stride (bytes)

template <int MODE>
__global__ __launch_bounds__(128, 2) void gemm_fp16_kernel(
    const __half* __restrict__ A, const __half* __restrict__ Bm,
    const float* __restrict__ bias, float* __restrict__ Cf,
    __half* __restrict__ Ch, int N, int K)
{
    extern __shared__ char sm[];
    const uint32_t sb = smem_u32(sm);
    const int tid  = threadIdx.x;
    const int lane = tid & 31;
    const int wid  = tid >> 5;
    const int brow = blockIdx.y * 128;
    const int bcol = blockIdx.x * 128;
    const int wm = (wid >> 1) * 64;
    const int wn = (wid & 1) * 64;
    const int chunks = K / 32;

    float acc[4][8][4];
#pragma unroll
    for (int i = 0; i < 4; i++)
#pragma unroll
        for (int j = 0; j < 8; j++)
#pragma unroll
            for (int r = 0; r < 4; r++) acc[i][j][r] = 0.0f;

    auto issue = [&](int ki, int buf) {
        const int k0 = ki * 32;
        const uint32_t bufo = sb + (uint32_t)buf * DSTG;
#pragma unroll
        for (int t = 0; t < 4; t++) {
            const int seg = tid + t * 128;
            const int row = seg >> 2, s = seg & 3;
            const uint32_t d = bufo + row * ROWB + s * 16;
            cp16(d,        A  + (size_t)(brow + row) * K + k0 + s * 8);
            cp16(d + D_AT, Bm + (size_t)(bcol + row) * K + k0 + s * 8);
        }
    };

    issue(0, 0); CP_COMMIT();
    issue(1, 1); CP_COMMIT();

    const uint32_t aoff = (wm + (lane & 15)) * ROWB + ((lane >> 4) & 1) * 16;
    const uint32_t boff = (wn + ((lane >> 4) & 1) * 8 + (lane & 7)) * ROWB +
                          ((lane >> 3) & 1) * 16;

    int rbuf = 0, wbuf = 2;
    for (int kc = 0; kc < chunks; kc++) {
        CP_WAIT(1);
        __syncthreads();
        if (kc + 2 < chunks) issue(kc + 2, wbuf);
        CP_COMMIT();

        const uint32_t base = sb + (uint32_t)rbuf * DSTG;
#pragma unroll
        for (int ks = 0; ks < 2; ks++) {
            uint32_t bq[4][4];
#pragma unroll
            for (int jp = 0; jp < 4; jp++)
                ldsm_x4(bq[jp], base + D_AT + boff + jp * (16 * ROWB) + ks * 32);
            uint32_t af[4][4];
#pragma unroll
            for (int i = 0; i < 4; i++)
                ldsm_x4(af[i], base + aoff + i * (16 * ROWB) + ks * 32);
#pragma unroll
            for (int i = 0; i < 4; i++)
#pragma unroll
                for (int j = 0; j < 8; j++)
                    mma_fp16(acc[i][j], af[i], &bq[j >> 1][(j & 1) * 2]);
        }
        rbuf = (rbuf == 2) ? 0 : rbuf + 1;
        wbuf = (wbuf == 2) ? 0 : wbuf + 1;
    }

    if (MODE == 0) {
#pragma unroll
        for (int i = 0; i < 4; i++) {
            const int r0 = brow + wm + i * 16 + (lane >> 2);
#pragma unroll
            for (int j = 0; j < 8; j++) {
                const int c0 = bcol + wn + j * 8 + 2 * (lane & 3);
                const float bx = __ldg(&bias[c0]), by = __ldg(&bias[c0 + 1]);
                float v00 = acc[i][j][0] + bx, v01 = acc[i][j][1] + by;
                float v10 = acc[i][j][2] + bx, v11 = acc[i][j][3] + by;
                *(float2*)(Cf + (size_t)r0 * N + c0)       = make_float2(v00, v01);
                *(float2*)(Cf + (size_t)(r0 + 8) * N + c0) = make_float2(v10, v11);
            }
        }
    } else {
        // Stage fp16 tile in smem (conflict-free STS), then coalesced 16B
        // stores to the column-block-major layout.
        __syncthreads();   // all warps done reading stage buffers
#pragma unroll
        for (int i = 0; i < 4; i++) {
            const int r0 = wm + i * 16 + (lane >> 2);
#pragma unroll
            for (int j = 0; j < 8; j++) {
                const int c0 = wn + j * 8 + 2 * (lane & 3);
                const float bx = __ldg(&bias[bcol + c0]);
                const float by = __ldg(&bias[bcol + c0 + 1]);
                float v00 = fmaxf(acc[i][j][0] + bx, 0.f);
                float v01 = fmaxf(acc[i][j][1] + by, 0.f);
                float v10 = fmaxf(acc[i][j][2] + bx, 0.f);
                float v11 = fmaxf(acc[i][j][3] + by, 0.f);
                *(__half2*)(sm + r0 * EP_ROWB + c0 * 2) =
                    __floats2half2_rn(v00, v01);
                *(__half2*)(sm + (r0 + 8) * EP_ROWB + c0 * 2) =
                    __floats2half2_rn(v10, v11);
            }
        }
        __syncthreads();
        // Copy out: 4 column blocks x 128 rows x 4 segs(16B) = 2048 segs.
        const int cb0 = bcol >> 5;
#pragma unroll
        for (int t = 0; t < 16; t++) {
            const int seg = tid + t * 128;
            const int cb  = seg >> 9;          // 0..3
            const int idx = seg & 511;
            const int row = idx >> 2, s = idx & 3;
            uint4 v = *(uint4*)(sm + row * EP_ROWB + cb * 64 + s * 16);
            *(uint4*)(Ch + (size_t)(cb0 + cb) * H1_BLK +
                      (size_t)(brow + row) * BSB + s * 8) = v;
        }
    }
}

// ---------------------------------------------------------------------------
// BSR layer: per (batch-tile 256, row-block rb):
//   h2[., rb*32:+32] = relu( sum_p h1b[col_p][b0:b0+256][.] @ vals[p]^T + b2 )
// A-gather is contiguous 16KB per block (blocked h1 layout).
// Plain fp16. 4 warps (64x32 warp tiles), 4-stage cp.async, ONE sync/block.
// smem 92KB -> 2 CTAs/SM.
// ---------------------------------------------------------------------------
#define S_AT   (256 * ROWB)                 // 20480 B (A tile)
#define S_BT   (32 * ROWB)                  // 2560 B  (B tile)
#define SSTG   (S_AT + S_BT)                // 23040 B per stage
#define SS     4
#define S_SMEM (SS * SSTG)                  // 92160 B

__global__ __launch_bounds__(128, 2) void bsr_fp16_kernel(
    const __half* __restrict__ h1b, const int* __restrict__ crow,
    const int* __restrict__ cols, const __half* __restrict__ vals,
    const float* __restrict__ bias, __half* __restrict__ h2)
{
    extern __shared__ char sm[];
    const uint32_t sb = smem_u32(sm);
    const int tid  = threadIdx.x;
    const int lane = tid & 31;
    const int wid  = tid >> 5;
    const int b0 = blockIdx.x * 256;
    const int rb = blockIdx.y;
    const int wm = wid * 64;    // 4 warps x 64 batch rows

    float acc[4][4][4];
#pragma unroll
    for (int i = 0; i < 4; i++)
#pragma unroll
        for (int j = 0; j < 4; j++)
#pragma unroll
            for (int r = 0; r < 4; r++) acc[i][j][r] = 0.0f;

    const int s0 = __ldg(&crow[rb]);
    const int nblk = __ldg(&crow[rb + 1]) - s0;

    auto issue = [&](int ki, int buf) {
        const int p = s0 + ki;
        const int cb = __ldg(&cols[p]);
        const uint32_t bufo = sb + (uint32_t)buf * SSTG;
        const __half* asrc = h1b + (size_t)cb * H1_BLK + (size_t)b0 * BSB;
#pragma unroll
        for (int t = 0; t < 8; t++) {
            const int seg = tid + t * 128;
            const int row = seg >> 2, s = seg & 3;
            cp16(bufo + row * ROWB + s * 16, asrc + (size_t)row * BSB + s * 8);
        }
        {
            const int row = tid >> 2, s = tid & 3;
            cp16(bufo + S_AT + row * ROWB + s * 16,
                 vals + (size_t)p * (BSB * BSB) + row * BSB + s * 8);
        }
    };

    issue(0, 0); CP_COMMIT();
    if (nblk > 1) issue(1, 1);
    CP_COMMIT();
    if (nblk > 2) issue(2, 2);
    CP_COMMIT();

    const uint32_t aoff = (wm + (lane & 15)) * ROWB + ((lane >> 4) & 1) * 16;
    const uint32_t boff = (((lane >> 4) & 1) * 8 + (lane & 7)) * ROWB +
                          ((lane >> 3) & 1) * 16;

    int rbuf = 0, wbuf = 3;
    for (int it = 0; it < nblk; it++) {
        CP_WAIT(2);
        __syncthreads();
        if (it + 3 < nblk) issue(it + 3, wbuf);
        CP_COMMIT();

        const uint32_t base = sb + (uint32_t)rbuf * SSTG;
#pragma unroll
        for (int ks = 0; ks < 2; ks++) {
            uint32_t bq[2][4];
#pragma unroll
            for (int jp = 0; jp < 2; jp++)
                ldsm_x4(bq[jp], base + S_AT + boff + jp * (16 * ROWB) + ks * 32);
            uint32_t af[4][4];
#pragma unroll
            for (int i = 0; i < 4; i++)
                ldsm_x4(af[i], base + aoff + i * (16 * ROWB) + ks * 32);
#pragma unroll
            for (int i = 0; i < 4; i++)
#pragma unroll
                for (int j = 0; j < 4; j++)
                    mma_fp16(acc[i][j], af[i], &bq[j >> 1][(j & 1) * 2]);
        }
        rbuf = (rbuf + 1) & 3;
        wbuf = (wbuf + 1) & 3;
    }

    // epilogue: bias + relu -> fp16 (row-major h2)
#pragma unroll
    for (int i = 0; i < 4; i++) {
        const int r0 = b0 + wm + i * 16 + (lane >> 2);
#pragma unroll
        for (int j = 0; j < 4; j++) {
            const int c0 = rb * 32 + j * 8 + 2 * (lane & 3);
            const float bx = __ldg(&bias[c0]), by = __ldg(&bias[c0 + 1]);
            float v00 = fmaxf(acc[i][j][0] + bx, 0.f);
            float v01 = fmaxf(acc[i][j][1] + by, 0.f);
            float v10 = fmaxf(acc[i][j][2] + bx, 0.f);
            float v11 = fmaxf(acc[i][j][3] + by, 0.f);
            *(__half2*)(h2 + (size_t)r0 * H_DIM + c0)       = __floats2half2_rn(v00, v01);
            *(__half2*)(h2 + (size_t)(r0 + 8) * H_DIM + c0) = __floats2half2_rn(v10, v11);
        }
    }
}

// ---------------------------------------------------------------------------
// Launcher
// ---------------------------------------------------------------------------
extern "C" void kernel_launch(void* const* d_in, const int* in_sizes, int n_in,
                              void* d_out, int out_size)
{
    const float* x    = (const float*)d_in[0];
    const float* W1   = (const float*)d_in[1];
    const float* b1   = (const float*)d_in[2];
    const int*   crow = (const int*)d_in[3];
    const int*   cols = (const int*)d_in[4];
    const float* vals = (const float*)d_in[5];
    const float* b2   = (const float*)d_in[6];
    const float* W3   = (const float*)d_in[7];
    const float* b3   = (const float*)d_in[8];
    float* out = (float*)d_out;

    __half *xh, *w1, *w3, *vf, *h1, *h2;
    cudaGetSymbolAddress((void**)&xh, g_x);
    cudaGetSymbolAddress((void**)&w1, g_w1);
    cudaGetSymbolAddress((void**)&w3, g_w3);
    cudaGetSymbolAddress((void**)&vf, g_vals);
    cudaGetSymbolAddress((void**)&h1, g_h1);
    cudaGetSymbolAddress((void**)&h2, g_h2);

    cudaFuncSetAttribute(gemm_fp16_kernel<0>,
                         cudaFuncAttributeMaxDynamicSharedMemorySize, D_SMEM);
    cudaFuncSetAttribute(gemm_fp16_kernel<1>,
                         cudaFuncAttributeMaxDynamicSharedMemorySize, D_SMEM);
    cudaFuncSetAttribute(bsr_fp16_kernel,
                         cudaFuncAttributeMaxDynamicSharedMemorySize, S_SMEM);

    // Prep: convert x, W1, W3, vals to fp16 (each 2M elements = 512K float4)
    const int n4 = (B_DIM * IN_DIM) / 4;
    PrepArgs pa;
    pa.src[0] = (const float4*)x;    pa.dst[0] = (uint2*)xh;
    pa.src[1] = (const float4*)W1;   pa.dst[1] = (uint2*)w1;
    pa.src[2] = (const float4*)W3;   pa.dst[2] = (uint2*)w3;
    pa.src[3] = (const float4*)vals; pa.dst[3] = (uint2*)vf;
    prep_kernel<<<dim3(n4 / 256, 4), 256>>>(pa, n4);

    // Layer 1: h1 = relu(x @ W1^T + b1) -> fp16, column-block-major
    gemm_fp16_kernel<1><<<dim3(H_DIM / 128, B_DIM / 128), 128, D_SMEM>>>(
        xh, w1, b1, nullptr, h1, H_DIM, IN_DIM);

    // Layer 2: h2 = relu(BSR(h1b) + b2) -> fp16 row-major   [grid 8x64]
    bsr_fp16_kernel<<<dim3(B_DIM / 256, RBX), 128, S_SMEM>>>(
        h1, crow, cols, vf, b2, h2);

    // Layer 3: out = h2 @ W3^T + b3 (fp32)                  [grid 8x16]
    gemm_fp16_kernel<0><<<dim3(OUT_DIM / 128, B_DIM / 128), 128, D_SMEM>>>(
        h2, w3, b3, out, nullptr, OUT_DIM, H_DIM);
}